// round 1
// baseline (speedup 1.0000x reference)
#include <cuda_runtime.h>

// FiberConv: out[b,t,o] = sum_{s,i} K[t,s,o,i] * x[b,s,i] + bias[o]
// K[t,s,o,i] = sum_a edge_attr[t,s,a] * W[o*IN+i, a]
//
// Collapsed to GEMM: C[B, 384] = x[B, 384] @ Bmat[384, 384]
//   row index of Bmat: si = s*32+i ; col: to = t*32+o
//   C row-major col index to = t*32+o  ==  required [B,T,OUT] layout.

#define T_DIM 12
#define S_DIM 12
#define ATTR  3
#define IN_D  32
#define OUT_D 32
#define BATCH 400000
#define NDIM  384   // T*OUT
#define KDIM  384   // S*IN

__device__ float g_Bmat[KDIM * NDIM];   // [si][to], 589 KB, lives in L2 during GEMM

// ---------------------------------------------------------------------------
// Tiny precompute: Bmat[si][to] = sum_a edge[t,s,a] * W[o*IN+i, a]
// ---------------------------------------------------------------------------
__global__ void fiber_precompute(const float* __restrict__ edge,
                                 const float* __restrict__ W) {
    int idx = blockIdx.x * blockDim.x + threadIdx.x;
    if (idx >= KDIM * NDIM) return;
    int si = idx / NDIM;
    int to = idx % NDIM;
    int s = si >> 5, i = si & 31;
    int t = to >> 5, o = to & 31;
    const float* e = edge + (t * S_DIM + s) * ATTR;
    const float* w = W + (o * IN_D + i) * ATTR;
    g_Bmat[idx] = e[0] * w[0] + e[1] * w[1] + e[2] * w[2];
}

// ---------------------------------------------------------------------------
// SGEMM: C[BATCH, 384] = A[BATCH, 384] @ g_Bmat[384, 384]  (+ bias[col % 32])
// Tiles: BM=128, BN=128, BK=16; 256 threads, 8x8 per thread.
// BATCH = 128*3125 exactly, NDIM = 128*3 exactly, KDIM = 16*24 exactly.
// ---------------------------------------------------------------------------
#define BM 128
#define BN 128
#define BK 16
#define TM 8
#define TN 8

__global__ __launch_bounds__(256, 2)
void fiber_gemm(const float* __restrict__ A,
                const float* __restrict__ bias,
                float* __restrict__ C) {
    __shared__ float As[BK][BM];   // A staged transposed: As[k][m]
    __shared__ float Bs[BK][BN];

    const int bn = blockIdx.x;          // 0..2
    const int bm = blockIdx.y;          // 0..3124
    const int tid = threadIdx.x;        // 0..255

    const float* Ablk = A + (size_t)bm * BM * KDIM;
    float* Cblk = C + (size_t)bm * BM * NDIM + (size_t)bn * BN;

    const int tm = (tid / 16) * TM;     // 0..120
    const int tn = (tid % 16) * TN;     // 0..120

    float acc[TM][TN] = {};

    for (int kt = 0; kt < KDIM; kt += BK) {
        // --- stage A tile (128 rows x 16 cols), transposed into As[k][m] ---
        #pragma unroll
        for (int j = 0; j < 2; j++) {
            int f  = tid * 2 + j;        // 0..511 float4 slots
            int r  = f >> 2;             // 0..127
            int c4 = (f & 3) * 4;        // 0,4,8,12
            float4 v = *(const float4*)(Ablk + (size_t)r * KDIM + kt + c4);
            As[c4 + 0][r] = v.x;
            As[c4 + 1][r] = v.y;
            As[c4 + 2][r] = v.z;
            As[c4 + 3][r] = v.w;
        }
        // --- stage B tile (16 rows x 128 cols) ---
        #pragma unroll
        for (int j = 0; j < 2; j++) {
            int f  = tid * 2 + j;        // 0..511
            int kr = f >> 5;             // 0..15
            int nc = (f & 31) * 4;       // 0..124
            *(float4*)(&Bs[kr][nc]) =
                *(const float4*)(g_Bmat + (size_t)(kt + kr) * NDIM + bn * BN + nc);
        }
        __syncthreads();

        #pragma unroll
        for (int k = 0; k < BK; k++) {
            float rm[TM], rn[TN];
            #pragma unroll
            for (int i = 0; i < TM; i += 4)
                *(float4*)(&rm[i]) = *(const float4*)(&As[k][tm + i]);
            #pragma unroll
            for (int j = 0; j < TN; j += 4)
                *(float4*)(&rn[j]) = *(const float4*)(&Bs[k][tn + j]);
            #pragma unroll
            for (int i = 0; i < TM; i++)
                #pragma unroll
                for (int j = 0; j < TN; j++)
                    acc[i][j] += rm[i] * rn[j];
        }
        __syncthreads();
    }

    // epilogue: add bias[o] where o = global_col % 32 (bias is zeros in this
    // dataset but the contract includes it)
    float bj[TN];
    #pragma unroll
    for (int j = 0; j < TN; j++)
        bj[j] = bias[(bn * BN + tn + j) & 31];

    #pragma unroll
    for (int i = 0; i < TM; i++) {
        #pragma unroll
        for (int j = 0; j < TN; j += 4) {
            float4 v = make_float4(acc[i][j + 0] + bj[j + 0],
                                   acc[i][j + 1] + bj[j + 1],
                                   acc[i][j + 2] + bj[j + 2],
                                   acc[i][j + 3] + bj[j + 3]);
            *(float4*)(Cblk + (size_t)(tm + i) * NDIM + tn + j) = v;
        }
    }
}

// ---------------------------------------------------------------------------
extern "C" void kernel_launch(void* const* d_in, const int* in_sizes, int n_in,
                              void* d_out, int out_size) {
    const float* x    = (const float*)d_in[0];   // [B, S, IN]  = [400000, 384]
    const float* edge = (const float*)d_in[1];   // [T, S, ATTR]
    const float* W    = (const float*)d_in[2];   // [OUT*IN, ATTR]
    const float* bias = (const float*)d_in[3];   // [OUT]
    float* out = (float*)d_out;                  // [B, T, OUT] = [400000, 384]

    fiber_precompute<<<(KDIM * NDIM + 255) / 256, 256>>>(edge, W);

    dim3 grid(NDIM / BN, BATCH / BM);            // (3, 3125)
    fiber_gemm<<<grid, 256>>>(x, bias, out);
}

// round 3
// speedup vs baseline: 2.0410x; 2.0410x over previous
#include <cuda_runtime.h>
#include <cuda_bf16.h>
#include <cstdint>

// FiberConv collapsed to GEMM: C[400000,384] = x[400000,384] @ Bt^T + bias
//   Bt[n=(t*32+o)][k=(s*32+i)] = sum_a edge[t,s,a] * W[o*32+i, a]
// fp32 accuracy via bf16 split:  x = xh + xl,  B = Bh + Bl
//   C ~= xh*Bh + xl*Bh + xh*Bl     (error ~2^-16 relative)
// Implemented with mma.sync.m16n8k16 (plain sm_103 ISA; tcgen05 unavailable
// because the harness targets compute_103 without the 'a' feature set).

#define NDIM 384
#define KDIM 384
#define BATCH 400000

#define BM 128
#define BN 128
#define BK 32
#define NTHREADS 256

// padded bf16 row stride for smem tiles: 40 elems = 80 bytes
#define SSTR 40
#define TILE_BYTES (128 * SSTR * 2)       // 10240
#define STAGE_BYTES (4 * TILE_BYTES)      // Ah, Al, Bh, Bl = 40960
#define SMEM_DYN (2 * STAGE_BYTES)        // 81920

// precomputed B operand, [n][k] row-major bf16 (hi and lo parts)
__device__ __nv_bfloat16 g_Bh[NDIM * KDIM];
__device__ __nv_bfloat16 g_Bl[NDIM * KDIM];

__global__ void fiber_precompute(const float* __restrict__ edge,
                                 const float* __restrict__ W) {
    int idx = blockIdx.x * blockDim.x + threadIdx.x;
    if (idx >= NDIM * KDIM) return;
    int n = idx / KDIM, k = idx % KDIM;
    int t = n >> 5, o = n & 31, s = k >> 5, i = k & 31;
    const float* e = edge + (t * 12 + s) * 3;
    const float* w = W + (o * 32 + i) * 3;
    float v = e[0] * w[0] + e[1] * w[1] + e[2] * w[2];
    __nv_bfloat16 h = __float2bfloat16(v);
    __nv_bfloat16 l = __float2bfloat16(v - __bfloat162float(h));
    g_Bh[idx] = h;
    g_Bl[idx] = l;
}

// ---------------- PTX helpers ----------------
__device__ __forceinline__ uint32_t smem_u32(const void* p) {
    uint32_t a;
    asm("{ .reg .u64 t; cvta.to.shared.u64 t, %1; cvt.u32.u64 %0, t; }" : "=r"(a) : "l"(p));
    return a;
}
__device__ __forceinline__ void ldsm_x4(uint32_t& r0, uint32_t& r1, uint32_t& r2,
                                        uint32_t& r3, uint32_t addr) {
    asm volatile("ldmatrix.sync.aligned.m8n8.x4.shared.b16 {%0,%1,%2,%3}, [%4];"
                 : "=r"(r0), "=r"(r1), "=r"(r2), "=r"(r3) : "r"(addr));
}
__device__ __forceinline__ void mma_bf16(float& d0, float& d1, float& d2, float& d3,
                                         uint32_t a0, uint32_t a1, uint32_t a2, uint32_t a3,
                                         uint32_t b0, uint32_t b1) {
    asm volatile(
        "mma.sync.aligned.m16n8k16.row.col.f32.bf16.bf16.f32 "
        "{%0,%1,%2,%3}, {%4,%5,%6,%7}, {%8,%9}, {%0,%1,%2,%3};"
        : "+f"(d0), "+f"(d1), "+f"(d2), "+f"(d3)
        : "r"(a0), "r"(a1), "r"(a2), "r"(a3), "r"(b0), "r"(b1));
}
__device__ __forceinline__ void cp_async16(uint32_t dst, const void* src) {
    asm volatile("cp.async.cg.shared.global [%0], [%1], 16;" :: "r"(dst), "l"(src));
}
#define CP_COMMIT() asm volatile("cp.async.commit_group;" ::: "memory")
#define CP_WAIT0()  asm volatile("cp.async.wait_group 0;" ::: "memory")

__device__ __forceinline__ uint2 split_pack(float a, float b, uint32_t& lo_out) {
    __nv_bfloat16 ha = __float2bfloat16(a), hb = __float2bfloat16(b);
    __nv_bfloat16 la = __float2bfloat16(a - __bfloat162float(ha));
    __nv_bfloat16 lb = __float2bfloat16(b - __bfloat162float(hb));
    uint2 r;
    r.x = ((uint32_t)__bfloat16_as_ushort(hb) << 16) | __bfloat16_as_ushort(ha);
    lo_out = ((uint32_t)__bfloat16_as_ushort(lb) << 16) | __bfloat16_as_ushort(la);
    r.y = 0;
    return r;
}

// ---------------- main GEMM ----------------
__global__ void __launch_bounds__(NTHREADS)
fiber_gemm_hmma(const float* __restrict__ x, const float* __restrict__ bias,
                float* __restrict__ out) {
    extern __shared__ char smem[];
    const uint32_t sbase = smem_u32(smem);

    const int tid  = threadIdx.x;
    const int lane = tid & 31;
    const int warp = tid >> 5;
    const int wm = warp >> 2;          // 0..1
    const int wn = warp & 3;           // 0..3
    const int bn = blockIdx.x;         // 0..2
    const int bm = blockIdx.y;         // 0..3124

    const float* xblk = x + (size_t)bm * BM * KDIM;
    const __nv_bfloat16* gBh = g_Bh + (size_t)bn * BN * KDIM;
    const __nv_bfloat16* gBl = g_Bl + (size_t)bn * BN * KDIM;

    float acc[4][4][4];
    #pragma unroll
    for (int a = 0; a < 4; a++)
        #pragma unroll
        for (int b = 0; b < 4; b++)
            #pragma unroll
            for (int c = 0; c < 4; c++) acc[a][b][c] = 0.f;

    // ldmatrix per-lane byte offsets (within a tile)
    const uint32_t a_lane_off = (uint32_t)((wm * 64 + (lane & 15)) * (SSTR * 2) + (lane >> 4) * 16);
    const uint32_t b_lane_off = (uint32_t)((wn * 32 + ((lane >> 4) << 3) + (lane & 7)) * (SSTR * 2)
                                           + ((lane >> 3) & 1) * 16);

    // per-thread load indices
    // x: 1024 float4 slots per chunk; 4 per thread
    // B: 512 16B slots per chunk per part; 2 per thread each part
    float4 xr[4];

    auto load_x = [&](int c) {
        #pragma unroll
        for (int it = 0; it < 4; it++) {
            int slot = it * NTHREADS + tid;
            int r = slot >> 3, c4 = (slot & 7) * 4;
            xr[it] = *(const float4*)(xblk + (size_t)r * KDIM + c * BK + c4);
        }
    };
    auto cp_B = [&](int c, int buf) {
        uint32_t dBh = sbase + buf * STAGE_BYTES + 2 * TILE_BYTES;
        uint32_t dBl = dBh + TILE_BYTES;
        #pragma unroll
        for (int it = 0; it < 2; it++) {
            int slot = it * NTHREADS + tid;
            int r = slot >> 2, seg = slot & 3;
            uint32_t doff = (uint32_t)(r * (SSTR * 2) + seg * 16);
            size_t goff = (size_t)r * KDIM + c * BK + seg * 8;
            cp_async16(dBh + doff, gBh + goff);
            cp_async16(dBl + doff, gBl + goff);
        }
        CP_COMMIT();
    };
    auto sts_x = [&](int buf) {
        uint32_t dAh = sbase + buf * STAGE_BYTES;
        uint32_t dAl = dAh + TILE_BYTES;
        #pragma unroll
        for (int it = 0; it < 4; it++) {
            int slot = it * NTHREADS + tid;
            int r = slot >> 3, c4 = (slot & 7) * 4;
            uint32_t lo01, lo23;
            uint2 h01 = split_pack(xr[it].x, xr[it].y, lo01);
            uint2 h23 = split_pack(xr[it].z, xr[it].w, lo23);
            uint2 uh, ul;
            uh.x = h01.x; uh.y = h23.x;
            ul.x = lo01;  ul.y = lo23;
            uint32_t doff = (uint32_t)(r * (SSTR * 2) + c4 * 2);
            asm volatile("st.shared.v2.b32 [%0], {%1,%2};" :: "r"(dAh + doff), "r"(uh.x), "r"(uh.y));
            asm volatile("st.shared.v2.b32 [%0], {%1,%2};" :: "r"(dAl + doff), "r"(ul.x), "r"(ul.y));
        }
    };

    // prologue: stage chunk 0 into buffer 0
    load_x(0);
    cp_B(0, 0);
    sts_x(0);
    CP_WAIT0();
    __syncthreads();

    const int NCHUNK = KDIM / BK;   // 12
    for (int c = 0; c < NCHUNK; c++) {
        const int buf = c & 1;
        if (c + 1 < NCHUNK) {
            load_x(c + 1);
            cp_B(c + 1, buf ^ 1);
        }

        // ---- compute on stage `buf` ----
        const uint32_t Ah = sbase + buf * STAGE_BYTES;
        const uint32_t Al = Ah + TILE_BYTES;
        const uint32_t Bh = Ah + 2 * TILE_BYTES;
        const uint32_t Bl = Ah + 3 * TILE_BYTES;

        #pragma unroll
        for (int ks = 0; ks < BK / 16; ks++) {
            const uint32_t kso = ks * 32;   // 16 bf16 = 32 bytes
            uint32_t af[4][4], bh[2][4], bl[2][4];
            #pragma unroll
            for (int mi = 0; mi < 4; mi++)
                ldsm_x4(af[mi][0], af[mi][1], af[mi][2], af[mi][3],
                        Ah + a_lane_off + mi * 16 * (SSTR * 2) + kso);
            #pragma unroll
            for (int pj = 0; pj < 2; pj++)
                ldsm_x4(bh[pj][0], bh[pj][1], bh[pj][2], bh[pj][3],
                        Bh + b_lane_off + pj * 16 * (SSTR * 2) + kso);
            #pragma unroll
            for (int pj = 0; pj < 2; pj++)
                ldsm_x4(bl[pj][0], bl[pj][1], bl[pj][2], bl[pj][3],
                        Bl + b_lane_off + pj * 16 * (SSTR * 2) + kso);

            // term 1: Ah * Bh ; term 2: Ah * Bl
            #pragma unroll
            for (int mi = 0; mi < 4; mi++) {
                #pragma unroll
                for (int ni = 0; ni < 4; ni++) {
                    mma_bf16(acc[mi][ni][0], acc[mi][ni][1], acc[mi][ni][2], acc[mi][ni][3],
                             af[mi][0], af[mi][1], af[mi][2], af[mi][3],
                             bh[ni >> 1][(ni & 1) * 2], bh[ni >> 1][(ni & 1) * 2 + 1]);
                    mma_bf16(acc[mi][ni][0], acc[mi][ni][1], acc[mi][ni][2], acc[mi][ni][3],
                             af[mi][0], af[mi][1], af[mi][2], af[mi][3],
                             bl[ni >> 1][(ni & 1) * 2], bl[ni >> 1][(ni & 1) * 2 + 1]);
                }
            }
            // term 3: Al * Bh
            #pragma unroll
            for (int mi = 0; mi < 4; mi++) {
                ldsm_x4(af[mi][0], af[mi][1], af[mi][2], af[mi][3],
                        Al + a_lane_off + mi * 16 * (SSTR * 2) + kso);
                #pragma unroll
                for (int ni = 0; ni < 4; ni++)
                    mma_bf16(acc[mi][ni][0], acc[mi][ni][1], acc[mi][ni][2], acc[mi][ni][3],
                             af[mi][0], af[mi][1], af[mi][2], af[mi][3],
                             bh[ni >> 1][(ni & 1) * 2], bh[ni >> 1][(ni & 1) * 2 + 1]);
            }
        }

        if (c + 1 < NCHUNK) {
            sts_x(buf ^ 1);
            CP_WAIT0();
        }
        __syncthreads();
    }

    // ---- epilogue: registers -> global (float2 stores) + bias ----
    float* oblk = out + (size_t)bm * BM * NDIM + bn * BN;
    const int r0 = wm * 64 + (lane >> 2);
    const int c0 = wn * 32 + (lane & 3) * 2;
    #pragma unroll
    for (int ni = 0; ni < 4; ni++) {
        const int col = c0 + ni * 8;
        const float b0 = bias[col & 31];
        const float b1 = bias[(col + 1) & 31];
        #pragma unroll
        for (int mi = 0; mi < 4; mi++) {
            const int row = r0 + mi * 16;
            float2 v0 = make_float2(acc[mi][ni][0] + b0, acc[mi][ni][1] + b1);
            float2 v1 = make_float2(acc[mi][ni][2] + b0, acc[mi][ni][3] + b1);
            *(float2*)(oblk + (size_t)row * NDIM + col) = v0;
            *(float2*)(oblk + (size_t)(row + 8) * NDIM + col) = v1;
        }
    }
}

// ---------------------------------------------------------------------------
extern "C" void kernel_launch(void* const* d_in, const int* in_sizes, int n_in,
                              void* d_out, int out_size) {
    const float* x    = (const float*)d_in[0];   // [400000, 384]
    const float* edge = (const float*)d_in[1];   // [12, 12, 3]
    const float* W    = (const float*)d_in[2];   // [1024, 3]
    const float* bias = (const float*)d_in[3];   // [32]
    float* out = (float*)d_out;                  // [400000, 384]

    cudaFuncSetAttribute(fiber_gemm_hmma,
                         cudaFuncAttributeMaxDynamicSharedMemorySize, SMEM_DYN);

    fiber_precompute<<<(NDIM * KDIM + 255) / 256, 256>>>(edge, W);

    dim3 grid(NDIM / BN, BATCH / BM);   // (3, 3125)
    fiber_gemm_hmma<<<grid, NTHREADS, SMEM_DYN>>>(x, bias, out);
}

// round 4
// speedup vs baseline: 2.7214x; 1.3334x over previous
#include <cuda_runtime.h>
#include <cuda_bf16.h>
#include <cstdint>

// FiberConv collapsed to GEMM: C[400000,384] = x[400000,384] @ Bt^T + bias
//   Bt[n=(t*32+o)][k=(s*32+i)] = sum_a edge[t,s,a] * W[o*32+i, a]
// fp32 accuracy via bf16 split:  x = xh + xl,  B = Bh + Bl
//   C ~= xh*Bh + xh*Bl + xl*Bh     (error ~2^-16 relative)
// mma.sync.m16n8k16 (plain sm_103 ISA; tcgen05 needs sm_103a target).
// R4: MMA issue reordered into 3 separated passes (kills the back-to-back
// same-accumulator RAW chain that capped tensor pipe at 46%), plus 2 CTAs/SM.

#define NDIM 384
#define KDIM 384
#define BATCH 400000

#define BM 128
#define BN 128
#define BK 32
#define NTHREADS 256

// padded bf16 row stride for smem tiles: 40 elems = 80 bytes
#define SSTR 40
#define TILE_BYTES (128 * SSTR * 2)       // 10240
#define STAGE_BYTES (4 * TILE_BYTES)      // Ah, Al, Bh, Bl = 40960
#define SMEM_DYN (2 * STAGE_BYTES)        // 81920

__device__ __nv_bfloat16 g_Bh[NDIM * KDIM];
__device__ __nv_bfloat16 g_Bl[NDIM * KDIM];

__global__ void fiber_precompute(const float* __restrict__ edge,
                                 const float* __restrict__ W) {
    int idx = blockIdx.x * blockDim.x + threadIdx.x;
    if (idx >= NDIM * KDIM) return;
    int n = idx / KDIM, k = idx % KDIM;
    int t = n >> 5, o = n & 31, s = k >> 5, i = k & 31;
    const float* e = edge + (t * 12 + s) * 3;
    const float* w = W + (o * 32 + i) * 3;
    float v = e[0] * w[0] + e[1] * w[1] + e[2] * w[2];
    __nv_bfloat16 h = __float2bfloat16(v);
    __nv_bfloat16 l = __float2bfloat16(v - __bfloat162float(h));
    g_Bh[idx] = h;
    g_Bl[idx] = l;
}

// ---------------- PTX helpers ----------------
__device__ __forceinline__ uint32_t smem_u32(const void* p) {
    uint32_t a;
    asm("{ .reg .u64 t; cvta.to.shared.u64 t, %1; cvt.u32.u64 %0, t; }" : "=r"(a) : "l"(p));
    return a;
}
__device__ __forceinline__ void ldsm_x4(uint32_t& r0, uint32_t& r1, uint32_t& r2,
                                        uint32_t& r3, uint32_t addr) {
    asm volatile("ldmatrix.sync.aligned.m8n8.x4.shared.b16 {%0,%1,%2,%3}, [%4];"
                 : "=r"(r0), "=r"(r1), "=r"(r2), "=r"(r3) : "r"(addr));
}
__device__ __forceinline__ void mma_bf16(float& d0, float& d1, float& d2, float& d3,
                                         uint32_t a0, uint32_t a1, uint32_t a2, uint32_t a3,
                                         uint32_t b0, uint32_t b1) {
    asm volatile(
        "mma.sync.aligned.m16n8k16.row.col.f32.bf16.bf16.f32 "
        "{%0,%1,%2,%3}, {%4,%5,%6,%7}, {%8,%9}, {%0,%1,%2,%3};"
        : "+f"(d0), "+f"(d1), "+f"(d2), "+f"(d3)
        : "r"(a0), "r"(a1), "r"(a2), "r"(a3), "r"(b0), "r"(b1));
}
__device__ __forceinline__ void cp_async16(uint32_t dst, const void* src) {
    asm volatile("cp.async.cg.shared.global [%0], [%1], 16;" :: "r"(dst), "l"(src));
}
#define CP_COMMIT() asm volatile("cp.async.commit_group;" ::: "memory")
#define CP_WAIT0()  asm volatile("cp.async.wait_group 0;" ::: "memory")

__device__ __forceinline__ uint32_t pack_hi(float a, float b, uint32_t& lo_out) {
    __nv_bfloat16 ha = __float2bfloat16(a), hb = __float2bfloat16(b);
    __nv_bfloat16 la = __float2bfloat16(a - __bfloat162float(ha));
    __nv_bfloat16 lb = __float2bfloat16(b - __bfloat162float(hb));
    lo_out = ((uint32_t)__bfloat16_as_ushort(lb) << 16) | __bfloat16_as_ushort(la);
    return ((uint32_t)__bfloat16_as_ushort(hb) << 16) | __bfloat16_as_ushort(ha);
}

// ---------------- main GEMM ----------------
__global__ void __launch_bounds__(NTHREADS, 2)
fiber_gemm_hmma(const float* __restrict__ x, const float* __restrict__ bias,
                float* __restrict__ out) {
    extern __shared__ char smem[];
    const uint32_t sbase = smem_u32(smem);

    const int tid  = threadIdx.x;
    const int lane = tid & 31;
    const int warp = tid >> 5;
    const int wm = warp >> 2;          // 0..1
    const int wn = warp & 3;           // 0..3
    const int bn = blockIdx.x;         // 0..2
    const int bm = blockIdx.y;         // 0..3124

    const float* xblk = x + (size_t)bm * BM * KDIM;
    const __nv_bfloat16* gBh = g_Bh + (size_t)bn * BN * KDIM;
    const __nv_bfloat16* gBl = g_Bl + (size_t)bn * BN * KDIM;

    float acc[4][4][4];
    #pragma unroll
    for (int a = 0; a < 4; a++)
        #pragma unroll
        for (int b = 0; b < 4; b++)
            #pragma unroll
            for (int c = 0; c < 4; c++) acc[a][b][c] = 0.f;

    const uint32_t a_lane_off = (uint32_t)((wm * 64 + (lane & 15)) * (SSTR * 2) + (lane >> 4) * 16);
    const uint32_t b_lane_off = (uint32_t)((wn * 32 + ((lane >> 4) << 3) + (lane & 7)) * (SSTR * 2)
                                           + ((lane >> 3) & 1) * 16);

    float4 xr[4];

    auto load_x = [&](int c) {
        #pragma unroll
        for (int it = 0; it < 4; it++) {
            int slot = it * NTHREADS + tid;
            int r = slot >> 3, c4 = (slot & 7) * 4;
            xr[it] = *(const float4*)(xblk + (size_t)r * KDIM + c * BK + c4);
        }
    };
    auto cp_B = [&](int c, int buf) {
        uint32_t dBh = sbase + buf * STAGE_BYTES + 2 * TILE_BYTES;
        uint32_t dBl = dBh + TILE_BYTES;
        #pragma unroll
        for (int it = 0; it < 2; it++) {
            int slot = it * NTHREADS + tid;
            int r = slot >> 2, seg = slot & 3;
            uint32_t doff = (uint32_t)(r * (SSTR * 2) + seg * 16);
            size_t goff = (size_t)r * KDIM + c * BK + seg * 8;
            cp_async16(dBh + doff, gBh + goff);
            cp_async16(dBl + doff, gBl + goff);
        }
        CP_COMMIT();
    };
    auto sts_x = [&](int buf) {
        uint32_t dAh = sbase + buf * STAGE_BYTES;
        uint32_t dAl = dAh + TILE_BYTES;
        #pragma unroll
        for (int it = 0; it < 4; it++) {
            int slot = it * NTHREADS + tid;
            int r = slot >> 3, c4 = (slot & 7) * 4;
            uint32_t lo01, lo23;
            uint32_t h01 = pack_hi(xr[it].x, xr[it].y, lo01);
            uint32_t h23 = pack_hi(xr[it].z, xr[it].w, lo23);
            uint32_t doff = (uint32_t)(r * (SSTR * 2) + c4 * 2);
            asm volatile("st.shared.v2.b32 [%0], {%1,%2};" :: "r"(dAh + doff), "r"(h01), "r"(h23));
            asm volatile("st.shared.v2.b32 [%0], {%1,%2};" :: "r"(dAl + doff), "r"(lo01), "r"(lo23));
        }
    };

    load_x(0);
    cp_B(0, 0);
    sts_x(0);
    CP_WAIT0();
    __syncthreads();

    const int NCHUNK = KDIM / BK;   // 12
    for (int c = 0; c < NCHUNK; c++) {
        const int buf = c & 1;
        if (c + 1 < NCHUNK) {
            load_x(c + 1);
            cp_B(c + 1, buf ^ 1);
        }

        const uint32_t Ah = sbase + buf * STAGE_BYTES;
        const uint32_t Al = Ah + TILE_BYTES;
        const uint32_t Bh = Ah + 2 * TILE_BYTES;
        const uint32_t Bl = Ah + 3 * TILE_BYTES;

        #pragma unroll
        for (int ks = 0; ks < BK / 16; ks++) {
            const uint32_t kso = ks * 32;
            uint32_t af[4][4], bh[2][4], bl[2][4];
            #pragma unroll
            for (int mi = 0; mi < 4; mi++)
                ldsm_x4(af[mi][0], af[mi][1], af[mi][2], af[mi][3],
                        Ah + a_lane_off + mi * 16 * (SSTR * 2) + kso);
            #pragma unroll
            for (int pj = 0; pj < 2; pj++)
                ldsm_x4(bh[pj][0], bh[pj][1], bh[pj][2], bh[pj][3],
                        Bh + b_lane_off + pj * 16 * (SSTR * 2) + kso);
            #pragma unroll
            for (int pj = 0; pj < 2; pj++)
                ldsm_x4(bl[pj][0], bl[pj][1], bl[pj][2], bl[pj][3],
                        Bl + b_lane_off + pj * 16 * (SSTR * 2) + kso);

            // pass 1: Ah * Bh — 16 independent MMAs
            #pragma unroll
            for (int mi = 0; mi < 4; mi++)
                #pragma unroll
                for (int ni = 0; ni < 4; ni++)
                    mma_bf16(acc[mi][ni][0], acc[mi][ni][1], acc[mi][ni][2], acc[mi][ni][3],
                             af[mi][0], af[mi][1], af[mi][2], af[mi][3],
                             bh[ni >> 1][(ni & 1) * 2], bh[ni >> 1][(ni & 1) * 2 + 1]);

            // pass 2: Ah * Bl — each acc re-touched 16 MMAs after pass 1
            #pragma unroll
            for (int mi = 0; mi < 4; mi++)
                #pragma unroll
                for (int ni = 0; ni < 4; ni++)
                    mma_bf16(acc[mi][ni][0], acc[mi][ni][1], acc[mi][ni][2], acc[mi][ni][3],
                             af[mi][0], af[mi][1], af[mi][2], af[mi][3],
                             bl[ni >> 1][(ni & 1) * 2], bl[ni >> 1][(ni & 1) * 2 + 1]);

            // pass 3: Al * Bh — reload A frags (reuse af regs; bl now dead)
            #pragma unroll
            for (int mi = 0; mi < 4; mi++)
                ldsm_x4(af[mi][0], af[mi][1], af[mi][2], af[mi][3],
                        Al + a_lane_off + mi * 16 * (SSTR * 2) + kso);
            #pragma unroll
            for (int mi = 0; mi < 4; mi++)
                #pragma unroll
                for (int ni = 0; ni < 4; ni++)
                    mma_bf16(acc[mi][ni][0], acc[mi][ni][1], acc[mi][ni][2], acc[mi][ni][3],
                             af[mi][0], af[mi][1], af[mi][2], af[mi][3],
                             bh[ni >> 1][(ni & 1) * 2], bh[ni >> 1][(ni & 1) * 2 + 1]);
        }

        if (c + 1 < NCHUNK) {
            sts_x(buf ^ 1);
            CP_WAIT0();
        }
        __syncthreads();
    }

    // ---- epilogue: registers -> global (float2 stores) + bias ----
    float* oblk = out + (size_t)bm * BM * NDIM + bn * BN;
    const int r0 = wm * 64 + (lane >> 2);
    const int c0 = wn * 32 + (lane & 3) * 2;
    #pragma unroll
    for (int ni = 0; ni < 4; ni++) {
        const int col = c0 + ni * 8;
        const float b0 = bias[col & 31];
        const float b1 = bias[(col + 1) & 31];
        #pragma unroll
        for (int mi = 0; mi < 4; mi++) {
            const int row = r0 + mi * 16;
            float2 v0 = make_float2(acc[mi][ni][0] + b0, acc[mi][ni][1] + b1);
            float2 v1 = make_float2(acc[mi][ni][2] + b0, acc[mi][ni][3] + b1);
            *(float2*)(oblk + (size_t)row * NDIM + col) = v0;
            *(float2*)(oblk + (size_t)(row + 8) * NDIM + col) = v1;
        }
    }
}

// ---------------------------------------------------------------------------
extern "C" void kernel_launch(void* const* d_in, const int* in_sizes, int n_in,
                              void* d_out, int out_size) {
    const float* x    = (const float*)d_in[0];   // [400000, 384]
    const float* edge = (const float*)d_in[1];   // [12, 12, 3]
    const float* W    = (const float*)d_in[2];   // [1024, 3]
    const float* bias = (const float*)d_in[3];   // [32]
    float* out = (float*)d_out;                  // [400000, 384]

    cudaFuncSetAttribute(fiber_gemm_hmma,
                         cudaFuncAttributeMaxDynamicSharedMemorySize, SMEM_DYN);

    fiber_precompute<<<(NDIM * KDIM + 255) / 256, 256>>>(edge, W);

    dim3 grid(NDIM / BN, BATCH / BM);   // (3, 3125)
    fiber_gemm_hmma<<<grid, NTHREADS, SMEM_DYN>>>(x, bias, out);
}